// round 15
// baseline (speedup 1.0000x reference)
#include <cuda_runtime.h>
#include <math.h>

// ---------------------------------------------------------------------------
// MS_MSA — exact fp32, f32x2 GEMMs. FIX: mask-buffer size constant was
// 13704448 (768 short of 122368*112=13705216) since R1 — overflow corrupted
// the ms tail -> 64 mask_attn entries -> stable 1.4475e-3 deviation.
// B=4, H=W=256, C=112, HEADS=4, D=28, N=65536, WP=478
// ---------------------------------------------------------------------------

#define CDIM 112
#define NPIX 65536
#define ROWS_TOTAL 262144   // 4*65536
#define MROWS 122368        // 256*478
#define MELEMS 13705216     // 122368*112  (was wrongly 13704448)
#define WPW 478

typedef unsigned long long u64;

__device__ __forceinline__ u64 pk2(float a) {
    u64 r; asm("mov.b64 %0, {%1, %1};" : "=l"(r) : "f"(a)); return r;
}
__device__ __forceinline__ u64 fma2(u64 a, u64 b, u64 c) {
    u64 d; asm("fma.rn.f32x2 %0, %1, %2, %3;" : "=l"(d) : "l"(a), "l"(b), "l"(c)); return d;
}
__device__ __forceinline__ float lo32(u64 v){ return __uint_as_float((unsigned)(v & 0xffffffffu)); }
__device__ __forceinline__ float hi32(u64 v){ return __uint_as_float((unsigned)(v >> 32)); }

// ------------------------- scratch (device globals) ------------------------
__device__ float g_q[29360128];
__device__ float g_k[29360128];
__device__ float g_v[29360128];
__device__ float g_xo[29360128];
__device__ float g_t1[29360128];
__device__ float g_pe[29360128];
__device__ float g_m1[13705216];
__device__ float g_m2[13705216];
__device__ float g_ms[13705216];
__device__ float g_ma[7340032];       // mask_attn [256,256,112]
__device__ float g_gram[12544];       // [4][4][28][28] normalized k.q
__device__ float g_nq[448];           // [4][112] sum of squares
__device__ float g_nk[448];
__device__ float g_attn[12544];
__device__ float g_Abd[50176];        // [4][112][112] block-diag apply matrix

// ------------------------------- zero kernel -------------------------------
__global__ void zero_small_kernel(float* gram) {
    int t = blockIdx.x * blockDim.x + threadIdx.x;
    if (t < 12544) gram[t] = 0.f;
}

// ------------------------- generic 112-wide GEMM ---------------------------
// out[r, o] = sum_i A'[r,i] * Weff[i,o]  (+bias) (+add);  exact fp32.
template<bool TRANSW, bool HAS_MUL, bool HAS_ADD, bool WPERB>
__global__ __launch_bounds__(224, 2)
void gemm112(const float* __restrict__ A, const float* __restrict__ W,
             const float* __restrict__ bias, const float* __restrict__ mul,
             const float* __restrict__ add, float* __restrict__ out, int rows)
{
    extern __shared__ float sm[];
    float* w_s = sm;                 // [112][112]
    float* x_s = sm + CDIM * CDIM;   // [128][113]
    const int tid = threadIdx.x;
    const int r0 = blockIdx.x * 128;

    const float* Wp = W;
    if (WPERB) Wp += (r0 >> 16) * (CDIM * CDIM);

    for (int e = tid; e < CDIM * CDIM; e += 224) {
        if (TRANSW) { int o = e / CDIM, i = e - o * CDIM; w_s[i * CDIM + o] = Wp[e]; }
        else        { w_s[e] = Wp[e]; }
    }
    for (int e = tid; e < 128 * CDIM; e += 224) {
        int r = e / CDIM, i = e - r * CDIM;
        int gr = r0 + r;
        float v = 0.f;
        if (gr < rows) {
            v = A[gr * CDIM + i];
            if (HAS_MUL) v = v * mul[(gr & (NPIX - 1)) * CDIM + i];
        }
        x_s[r * 113 + i] = v;
    }
    __syncthreads();

    const int rg = tid / 14, cg = tid - rg * 14;
    const int o0 = cg * 8;
    const int rbase = rg * 8;
    u64 acc[8][4];
    #pragma unroll
    for (int a = 0; a < 8; a++)
        #pragma unroll
        for (int b = 0; b < 4; b++) acc[a][b] = 0ull;

    const float* xp = &x_s[rbase * 113];
    #pragma unroll 4
    for (int i = 0; i < CDIM; i++) {
        ulonglong2 w0 = *reinterpret_cast<const ulonglong2*>(&w_s[i * CDIM + o0]);
        ulonglong2 w1 = *reinterpret_cast<const ulonglong2*>(&w_s[i * CDIM + o0 + 4]);
        #pragma unroll
        for (int rr = 0; rr < 8; rr++) {
            u64 xx = pk2(xp[rr * 113 + i]);
            acc[rr][0] = fma2(xx, w0.x, acc[rr][0]);
            acc[rr][1] = fma2(xx, w0.y, acc[rr][1]);
            acc[rr][2] = fma2(xx, w1.x, acc[rr][2]);
            acc[rr][3] = fma2(xx, w1.y, acc[rr][3]);
        }
    }

    #pragma unroll
    for (int rr = 0; rr < 8; rr++) {
        int gr = r0 + rbase + rr;
        if (gr >= rows) continue;
        float o_[8];
        o_[0] = lo32(acc[rr][0]); o_[1] = hi32(acc[rr][0]);
        o_[2] = lo32(acc[rr][1]); o_[3] = hi32(acc[rr][1]);
        o_[4] = lo32(acc[rr][2]); o_[5] = hi32(acc[rr][2]);
        o_[6] = lo32(acc[rr][3]); o_[7] = hi32(acc[rr][3]);
        #pragma unroll
        for (int cc = 0; cc < 8; cc++) {
            float vv = o_[cc];
            if (bias)    vv += bias[o0 + cc];
            if (HAS_ADD) vv += add[gr * CDIM + o0 + cc];
            o_[cc] = vv;
        }
        float4* op = reinterpret_cast<float4*>(&out[gr * CDIM + o0]);
        op[0] = make_float4(o_[0], o_[1], o_[2], o_[3]);
        op[1] = make_float4(o_[4], o_[5], o_[6], o_[7]);
    }
}

// --------------- 5x5 depthwise + sigmoid + combine (ms = m1*amap + m1) -----
__global__ void mask_dw_kernel(const float* __restrict__ m1, const float* __restrict__ m2,
                               const float* __restrict__ dww, const float* __restrict__ dwb,
                               float* __restrict__ ms)
{
    __shared__ float w_s[112 * 25];
    __shared__ float b_s[112];
    for (int e = threadIdx.x; e < 112 * 25; e += blockDim.x) w_s[e] = dww[e];
    if (threadIdx.x < 112) b_s[threadIdx.x] = dwb[threadIdx.x];
    __syncthreads();
    int idx = blockIdx.x * blockDim.x + threadIdx.x;
    if (idx >= MELEMS) return;
    int ch = idx % CDIM;
    int p = idx / CDIM;
    int xc = p % WPW;
    int y = p / WPW;
    float acc = b_s[ch];
    #pragma unroll
    for (int dy = -2; dy <= 2; dy++) {
        int yy = y + dy;
        if ((unsigned)yy >= 256u) continue;
        #pragma unroll
        for (int dx = -2; dx <= 2; dx++) {
            int xx = xc + dx;
            if ((unsigned)xx >= (unsigned)WPW) continue;
            acc = fmaf(m2[(yy * WPW + xx) * CDIM + ch],
                       w_s[ch * 25 + (dy + 2) * 5 + (dx + 2)], acc);
        }
    }
    float amap = 1.f / (1.f + expf(-acc));
    float m1v = m1[idx];
    ms[idx] = m1v * amap + m1v;
}

// --------------------------- per-channel shift -----------------------------
// mask_attn[y, xo, ch] = ms[y, 2*ch + xo, ch]
__global__ void shift_kernel(const float* __restrict__ ms, float* __restrict__ ma)
{
    int idx = blockIdx.x * blockDim.x + threadIdx.x;
    if (idx >= 7340032) return;
    int ch = idx % CDIM;
    int p = idx / CDIM;
    int xo = p % 256;
    int y = p / 256;
    ma[idx] = ms[(y * WPW + 2 * ch + xo) * CDIM + ch];
}

// --------------------- literal per-(b,c) column norms ----------------------
__global__ void norm_lit_kernel(const float* __restrict__ x, float* __restrict__ outp)
{
    __shared__ float red[256];
    int c = blockIdx.x, b = blockIdx.y;
    float s = 0.f;
    for (int n = threadIdx.x; n < NPIX; n += 256) {
        float v = x[(b * NPIX + n) * CDIM + c];
        s = fmaf(v, v, s);
    }
    red[threadIdx.x] = s;
    __syncthreads();
    for (int st = 128; st > 0; st >>= 1) {
        if (threadIdx.x < st) red[threadIdx.x] += red[threadIdx.x + st];
        __syncthreads();
    }
    if (threadIdx.x == 0) outp[b * CDIM + c] = red[0];
}

// ---------- literal gram: thread (d,e) owns attn[b,h,d,e] partial ----------
__global__ void gram_lit_kernel(const float* __restrict__ q, const float* __restrict__ k,
                                const float* __restrict__ nqs, const float* __restrict__ nks,
                                float* __restrict__ gram)
{
    __shared__ float qt[64][29];
    __shared__ float kt[64][29];
    __shared__ float qn[28], kn[28];
    const int bh = blockIdx.y;
    const int b = bh >> 2, h = bh & 3;
    const int base = b * NPIX + blockIdx.x * 512;
    const int t = threadIdx.x;

    if (t < 28)      qn[t]      = fmaxf(sqrtf(nqs[b * CDIM + h * 28 + t]), 1e-12f);
    else if (t < 56) kn[t - 28] = fmaxf(sqrtf(nks[b * CDIM + h * 28 + (t - 28)]), 1e-12f);
    __syncthreads();

    const int d = t / 28, e = t - d * 28;
    float acc = 0.f;
    for (int c0 = 0; c0 < 512; c0 += 64) {
        for (int i = t; i < 64 * 28; i += 784) {
            int rr = i / 28, ch = i - rr * 28;
            int r = base + c0 + rr;
            qt[rr][ch] = q[r * CDIM + h * 28 + ch] / qn[ch];
            kt[rr][ch] = k[r * CDIM + h * 28 + ch] / kn[ch];
        }
        __syncthreads();
        #pragma unroll 8
        for (int rr = 0; rr < 64; rr++)
            acc = fmaf(kt[rr][d], qt[rr][e], acc);
        __syncthreads();
    }
    atomicAdd(&gram[bh * 784 + d * 28 + e], acc);
}

// ------------------ finalize attention: rescale + softmax ------------------
__global__ void attn_softmax_kernel(const float* __restrict__ gram, const float* __restrict__ rescale,
                                    float* __restrict__ attn)
{
    __shared__ float s[28][28];
    __shared__ float sex[28][28];
    int bh = blockIdx.x;
    int h = bh & 3;
    int t = threadIdx.x;
    int d = t / 28, e = t - d * 28;
    float v = gram[bh * 784 + d * 28 + e] * rescale[h];
    s[d][e] = v;
    __syncthreads();
    float m = -1e30f;
    for (int j = 0; j < 28; j++) m = fmaxf(m, s[d][j]);
    float ex = expf(v - m);
    sex[d][e] = ex;
    __syncthreads();
    float sum = 0.f;
    for (int j = 0; j < 28; j++) sum += sex[d][j];
    attn[bh * 784 + d * 28 + e] = ex / sum;
}

// ---- build block-diagonal apply matrix: Abd[b][h*28+e][h*28+d]=attn[b,h,d,e]
__global__ void build_abd_kernel(const float* __restrict__ attn, float* __restrict__ Abd)
{
    int b = blockIdx.x;
    float* A = Abd + b * (CDIM * CDIM);
    for (int i = threadIdx.x; i < CDIM * CDIM; i += blockDim.x) A[i] = 0.f;
    __syncthreads();
    for (int t = threadIdx.x; t < 4 * 784; t += blockDim.x) {
        int h = t / 784;
        int r = t - h * 784;
        int d = r / 28, e = r - d * 28;
        A[(h * 28 + e) * CDIM + (h * 28 + d)] = attn[((b * 4 + h) * 28 + d) * 28 + e];
    }
}

// -------------------- 3x3 depthwise conv (+optional GELU) ------------------
__global__ void dw3x3_kernel(const float* __restrict__ in, const float* __restrict__ w,
                             float* __restrict__ outp, int do_gelu)
{
    __shared__ float w_s[112 * 9];
    for (int e = threadIdx.x; e < 1008; e += blockDim.x) w_s[e] = w[e];
    __syncthreads();
    int idx = blockIdx.x * blockDim.x + threadIdx.x;
    if (idx >= 29360128) return;
    int ch = idx % CDIM;
    int p = idx / CDIM;
    int x = p % 256;
    int rest = p / 256;
    int y = rest % 256;
    int b = rest / 256;
    float acc = 0.f;
    #pragma unroll
    for (int dy = -1; dy <= 1; dy++) {
        int yy = y + dy;
        if ((unsigned)yy >= 256u) continue;
        #pragma unroll
        for (int dx = -1; dx <= 1; dx++) {
            int xx = x + dx;
            if ((unsigned)xx >= 256u) continue;
            acc = fmaf(in[((b * 256 + yy) * 256 + xx) * CDIM + ch],
                       w_s[ch * 9 + (dy + 1) * 3 + (dx + 1)], acc);
        }
    }
    if (do_gelu) acc = 0.5f * acc * (1.f + erff(acc * 0.70710678118654752f));
    outp[idx] = acc;
}

// ------------------------------- launch ------------------------------------
extern "C" void kernel_launch(void* const* d_in, const int* in_sizes, int n_in,
                              void* d_out, int out_size)
{
    const float* x_in    = (const float*)d_in[0];
    const float* mask    = (const float*)d_in[1];
    const float* Wq      = (const float*)d_in[2];
    const float* Wk      = (const float*)d_in[3];
    const float* Wv      = (const float*)d_in[4];
    const float* rescale = (const float*)d_in[5];
    const float* proj_w  = (const float*)d_in[6];
    const float* proj_b  = (const float*)d_in[7];
    const float* pe_w1   = (const float*)d_in[8];
    const float* pe_w2   = (const float*)d_in[9];
    const float* c1w     = (const float*)d_in[10];
    const float* c1b     = (const float*)d_in[11];
    const float* c2w     = (const float*)d_in[12];
    const float* c2b     = (const float*)d_in[13];
    const float* dww     = (const float*)d_in[14];
    const float* dwb     = (const float*)d_in[15];
    float* out = (float*)d_out;

    float *q, *k, *v, *xo, *t1, *pe, *m1, *m2, *ms, *ma, *gram, *nq, *nk, *attn, *Abd;
    cudaGetSymbolAddress((void**)&q,    g_q);
    cudaGetSymbolAddress((void**)&k,    g_k);
    cudaGetSymbolAddress((void**)&v,    g_v);
    cudaGetSymbolAddress((void**)&xo,   g_xo);
    cudaGetSymbolAddress((void**)&t1,   g_t1);
    cudaGetSymbolAddress((void**)&pe,   g_pe);
    cudaGetSymbolAddress((void**)&m1,   g_m1);
    cudaGetSymbolAddress((void**)&m2,   g_m2);
    cudaGetSymbolAddress((void**)&ms,   g_ms);
    cudaGetSymbolAddress((void**)&ma,   g_ma);
    cudaGetSymbolAddress((void**)&gram, g_gram);
    cudaGetSymbolAddress((void**)&nq,   g_nq);
    cudaGetSymbolAddress((void**)&nk,   g_nk);
    cudaGetSymbolAddress((void**)&attn, g_attn);
    cudaGetSymbolAddress((void**)&Abd,  g_Abd);

    const size_t smem = (CDIM * CDIM + 128 * 113) * sizeof(float); // 108032
    cudaFuncSetAttribute((const void*)gemm112<true,  false, false, false>,
                         cudaFuncAttributeMaxDynamicSharedMemorySize, (int)smem);
    cudaFuncSetAttribute((const void*)gemm112<false, false, false, false>,
                         cudaFuncAttributeMaxDynamicSharedMemorySize, (int)smem);
    cudaFuncSetAttribute((const void*)gemm112<false, true,  false, true>,
                         cudaFuncAttributeMaxDynamicSharedMemorySize, (int)smem);
    cudaFuncSetAttribute((const void*)gemm112<false, false, true,  false>,
                         cudaFuncAttributeMaxDynamicSharedMemorySize, (int)smem);

    // 0) zero gram accumulator (fresh every replay for determinism)
    zero_small_kernel<<<49, 256>>>(gram);

    // 1) mask pipeline (exact fp32) — grid/bounds now cover all 13,705,216
    gemm112<true,  false, false, false><<<956, 224, smem>>>(mask, c1w, c1b, nullptr, nullptr, m1, MROWS);
    gemm112<true,  false, false, false><<<956, 224, smem>>>(m1,   c2w, c2b, nullptr, nullptr, m2, MROWS);
    mask_dw_kernel<<<53536, 256>>>(m1, m2, dww, dwb, ms);
    shift_kernel<<<28672, 256>>>(ms, ma);

    // 2) QKV projections (exact fp32, packed f32x2)
    gemm112<false, false, false, false><<<2048, 224, smem>>>(x_in, Wq, nullptr, nullptr, nullptr, q, ROWS_TOTAL);
    gemm112<false, false, false, false><<<2048, 224, smem>>>(x_in, Wk, nullptr, nullptr, nullptr, k, ROWS_TOTAL);
    gemm112<false, false, false, false><<<2048, 224, smem>>>(x_in, Wv, nullptr, nullptr, nullptr, v, ROWS_TOTAL);

    // 3) literal column norms, then literal normalized gram (exact fp32)
    norm_lit_kernel<<<dim3(CDIM, 4), 256>>>(q, nq);
    norm_lit_kernel<<<dim3(CDIM, 4), 256>>>(k, nk);
    gram_lit_kernel<<<dim3(128, 16), 784>>>(q, k, nq, nk, gram);

    // 4) rescale + softmax; build block-diagonal apply matrix
    attn_softmax_kernel<<<16, 784>>>(gram, rescale, attn);
    build_abd_kernel<<<4, 256>>>(attn, Abd);

    // 5) positional-encoding branch (exact fp32)
    dw3x3_kernel<<<114688, 256>>>(v,  pe_w1, t1, 1);
    dw3x3_kernel<<<114688, 256>>>(t1, pe_w2, pe, 0);

    // 6) attention apply: xo = (v ⊙ ma) @ Abd[b]
    gemm112<false, true,  false, true ><<<2048, 224, smem>>>(v, Abd, nullptr, ma, nullptr, xo, ROWS_TOTAL);

    // 7) output projection: out = xo @ proj_w + proj_b + pe
    gemm112<false, false, true,  false><<<2048, 224, smem>>>(xo, proj_w, proj_b, nullptr, pe, out, ROWS_TOTAL);
}

// round 16
// speedup vs baseline: 1.0126x; 1.0126x over previous
#include <cuda_runtime.h>
#include <math.h>

// ---------------------------------------------------------------------------
// MS_MSA — exact fp32, f32x2 GEMMs. FIX: mask-buffer size constant was
// 13704448 (768 short of 122368*112=13705216) since R1 — overflow corrupted
// the ms tail -> 64 mask_attn entries -> stable 1.4475e-3 deviation.
// B=4, H=W=256, C=112, HEADS=4, D=28, N=65536, WP=478
// ---------------------------------------------------------------------------

#define CDIM 112
#define NPIX 65536
#define ROWS_TOTAL 262144   // 4*65536
#define MROWS 122368        // 256*478
#define MELEMS 13705216     // 122368*112  (was wrongly 13704448)
#define WPW 478

typedef unsigned long long u64;

__device__ __forceinline__ u64 pk2(float a) {
    u64 r; asm("mov.b64 %0, {%1, %1};" : "=l"(r) : "f"(a)); return r;
}
__device__ __forceinline__ u64 fma2(u64 a, u64 b, u64 c) {
    u64 d; asm("fma.rn.f32x2 %0, %1, %2, %3;" : "=l"(d) : "l"(a), "l"(b), "l"(c)); return d;
}
__device__ __forceinline__ float lo32(u64 v){ return __uint_as_float((unsigned)(v & 0xffffffffu)); }
__device__ __forceinline__ float hi32(u64 v){ return __uint_as_float((unsigned)(v >> 32)); }

// ------------------------- scratch (device globals) ------------------------
__device__ float g_q[29360128];
__device__ float g_k[29360128];
__device__ float g_v[29360128];
__device__ float g_xo[29360128];
__device__ float g_t1[29360128];
__device__ float g_pe[29360128];
__device__ float g_m1[13705216];
__device__ float g_m2[13705216];
__device__ float g_ms[13705216];
__device__ float g_ma[7340032];       // mask_attn [256,256,112]
__device__ float g_gram[12544];       // [4][4][28][28] normalized k.q
__device__ float g_nq[448];           // [4][112] sum of squares
__device__ float g_nk[448];
__device__ float g_attn[12544];
__device__ float g_Abd[50176];        // [4][112][112] block-diag apply matrix

// ------------------------------- zero kernel -------------------------------
__global__ void zero_small_kernel(float* gram) {
    int t = blockIdx.x * blockDim.x + threadIdx.x;
    if (t < 12544) gram[t] = 0.f;
}

// ------------------------- generic 112-wide GEMM ---------------------------
// out[r, o] = sum_i A'[r,i] * Weff[i,o]  (+bias) (+add);  exact fp32.
template<bool TRANSW, bool HAS_MUL, bool HAS_ADD, bool WPERB>
__global__ __launch_bounds__(224, 2)
void gemm112(const float* __restrict__ A, const float* __restrict__ W,
             const float* __restrict__ bias, const float* __restrict__ mul,
             const float* __restrict__ add, float* __restrict__ out, int rows)
{
    extern __shared__ float sm[];
    float* w_s = sm;                 // [112][112]
    float* x_s = sm + CDIM * CDIM;   // [128][113]
    const int tid = threadIdx.x;
    const int r0 = blockIdx.x * 128;

    const float* Wp = W;
    if (WPERB) Wp += (r0 >> 16) * (CDIM * CDIM);

    for (int e = tid; e < CDIM * CDIM; e += 224) {
        if (TRANSW) { int o = e / CDIM, i = e - o * CDIM; w_s[i * CDIM + o] = Wp[e]; }
        else        { w_s[e] = Wp[e]; }
    }
    for (int e = tid; e < 128 * CDIM; e += 224) {
        int r = e / CDIM, i = e - r * CDIM;
        int gr = r0 + r;
        float v = 0.f;
        if (gr < rows) {
            v = A[gr * CDIM + i];
            if (HAS_MUL) v = v * mul[(gr & (NPIX - 1)) * CDIM + i];
        }
        x_s[r * 113 + i] = v;
    }
    __syncthreads();

    const int rg = tid / 14, cg = tid - rg * 14;
    const int o0 = cg * 8;
    const int rbase = rg * 8;
    u64 acc[8][4];
    #pragma unroll
    for (int a = 0; a < 8; a++)
        #pragma unroll
        for (int b = 0; b < 4; b++) acc[a][b] = 0ull;

    const float* xp = &x_s[rbase * 113];
    #pragma unroll 4
    for (int i = 0; i < CDIM; i++) {
        ulonglong2 w0 = *reinterpret_cast<const ulonglong2*>(&w_s[i * CDIM + o0]);
        ulonglong2 w1 = *reinterpret_cast<const ulonglong2*>(&w_s[i * CDIM + o0 + 4]);
        #pragma unroll
        for (int rr = 0; rr < 8; rr++) {
            u64 xx = pk2(xp[rr * 113 + i]);
            acc[rr][0] = fma2(xx, w0.x, acc[rr][0]);
            acc[rr][1] = fma2(xx, w0.y, acc[rr][1]);
            acc[rr][2] = fma2(xx, w1.x, acc[rr][2]);
            acc[rr][3] = fma2(xx, w1.y, acc[rr][3]);
        }
    }

    #pragma unroll
    for (int rr = 0; rr < 8; rr++) {
        int gr = r0 + rbase + rr;
        if (gr >= rows) continue;
        float o_[8];
        o_[0] = lo32(acc[rr][0]); o_[1] = hi32(acc[rr][0]);
        o_[2] = lo32(acc[rr][1]); o_[3] = hi32(acc[rr][1]);
        o_[4] = lo32(acc[rr][2]); o_[5] = hi32(acc[rr][2]);
        o_[6] = lo32(acc[rr][3]); o_[7] = hi32(acc[rr][3]);
        #pragma unroll
        for (int cc = 0; cc < 8; cc++) {
            float vv = o_[cc];
            if (bias)    vv += bias[o0 + cc];
            if (HAS_ADD) vv += add[gr * CDIM + o0 + cc];
            o_[cc] = vv;
        }
        float4* op = reinterpret_cast<float4*>(&out[gr * CDIM + o0]);
        op[0] = make_float4(o_[0], o_[1], o_[2], o_[3]);
        op[1] = make_float4(o_[4], o_[5], o_[6], o_[7]);
    }
}

// --------------- 5x5 depthwise + sigmoid + combine (ms = m1*amap + m1) -----
__global__ void mask_dw_kernel(const float* __restrict__ m1, const float* __restrict__ m2,
                               const float* __restrict__ dww, const float* __restrict__ dwb,
                               float* __restrict__ ms)
{
    __shared__ float w_s[112 * 25];
    __shared__ float b_s[112];
    for (int e = threadIdx.x; e < 112 * 25; e += blockDim.x) w_s[e] = dww[e];
    if (threadIdx.x < 112) b_s[threadIdx.x] = dwb[threadIdx.x];
    __syncthreads();
    int idx = blockIdx.x * blockDim.x + threadIdx.x;
    if (idx >= MELEMS) return;
    int ch = idx % CDIM;
    int p = idx / CDIM;
    int xc = p % WPW;
    int y = p / WPW;
    float acc = b_s[ch];
    #pragma unroll
    for (int dy = -2; dy <= 2; dy++) {
        int yy = y + dy;
        if ((unsigned)yy >= 256u) continue;
        #pragma unroll
        for (int dx = -2; dx <= 2; dx++) {
            int xx = xc + dx;
            if ((unsigned)xx >= (unsigned)WPW) continue;
            acc = fmaf(m2[(yy * WPW + xx) * CDIM + ch],
                       w_s[ch * 25 + (dy + 2) * 5 + (dx + 2)], acc);
        }
    }
    float amap = 1.f / (1.f + expf(-acc));
    float m1v = m1[idx];
    ms[idx] = m1v * amap + m1v;
}

// --------------------------- per-channel shift -----------------------------
// mask_attn[y, xo, ch] = ms[y, 2*ch + xo, ch]
__global__ void shift_kernel(const float* __restrict__ ms, float* __restrict__ ma)
{
    int idx = blockIdx.x * blockDim.x + threadIdx.x;
    if (idx >= 7340032) return;
    int ch = idx % CDIM;
    int p = idx / CDIM;
    int xo = p % 256;
    int y = p / 256;
    ma[idx] = ms[(y * WPW + 2 * ch + xo) * CDIM + ch];
}

// --------------------- literal per-(b,c) column norms ----------------------
__global__ void norm_lit_kernel(const float* __restrict__ x, float* __restrict__ outp)
{
    __shared__ float red[256];
    int c = blockIdx.x, b = blockIdx.y;
    float s = 0.f;
    for (int n = threadIdx.x; n < NPIX; n += 256) {
        float v = x[(b * NPIX + n) * CDIM + c];
        s = fmaf(v, v, s);
    }
    red[threadIdx.x] = s;
    __syncthreads();
    for (int st = 128; st > 0; st >>= 1) {
        if (threadIdx.x < st) red[threadIdx.x] += red[threadIdx.x + st];
        __syncthreads();
    }
    if (threadIdx.x == 0) outp[b * CDIM + c] = red[0];
}

// ---------- literal gram: thread (d,e) owns attn[b,h,d,e] partial ----------
__global__ void gram_lit_kernel(const float* __restrict__ q, const float* __restrict__ k,
                                const float* __restrict__ nqs, const float* __restrict__ nks,
                                float* __restrict__ gram)
{
    __shared__ float qt[64][29];
    __shared__ float kt[64][29];
    __shared__ float qn[28], kn[28];
    const int bh = blockIdx.y;
    const int b = bh >> 2, h = bh & 3;
    const int base = b * NPIX + blockIdx.x * 512;
    const int t = threadIdx.x;

    if (t < 28)      qn[t]      = fmaxf(sqrtf(nqs[b * CDIM + h * 28 + t]), 1e-12f);
    else if (t < 56) kn[t - 28] = fmaxf(sqrtf(nks[b * CDIM + h * 28 + (t - 28)]), 1e-12f);
    __syncthreads();

    const int d = t / 28, e = t - d * 28;
    float acc = 0.f;
    for (int c0 = 0; c0 < 512; c0 += 64) {
        for (int i = t; i < 64 * 28; i += 784) {
            int rr = i / 28, ch = i - rr * 28;
            int r = base + c0 + rr;
            qt[rr][ch] = q[r * CDIM + h * 28 + ch] / qn[ch];
            kt[rr][ch] = k[r * CDIM + h * 28 + ch] / kn[ch];
        }
        __syncthreads();
        #pragma unroll 8
        for (int rr = 0; rr < 64; rr++)
            acc = fmaf(kt[rr][d], qt[rr][e], acc);
        __syncthreads();
    }
    atomicAdd(&gram[bh * 784 + d * 28 + e], acc);
}

// ------------------ finalize attention: rescale + softmax ------------------
__global__ void attn_softmax_kernel(const float* __restrict__ gram, const float* __restrict__ rescale,
                                    float* __restrict__ attn)
{
    __shared__ float s[28][28];
    __shared__ float sex[28][28];
    int bh = blockIdx.x;
    int h = bh & 3;
    int t = threadIdx.x;
    int d = t / 28, e = t - d * 28;
    float v = gram[bh * 784 + d * 28 + e] * rescale[h];
    s[d][e] = v;
    __syncthreads();
    float m = -1e30f;
    for (int j = 0; j < 28; j++) m = fmaxf(m, s[d][j]);
    float ex = expf(v - m);
    sex[d][e] = ex;
    __syncthreads();
    float sum = 0.f;
    for (int j = 0; j < 28; j++) sum += sex[d][j];
    attn[bh * 784 + d * 28 + e] = ex / sum;
}

// ---- build block-diagonal apply matrix: Abd[b][h*28+e][h*28+d]=attn[b,h,d,e]
__global__ void build_abd_kernel(const float* __restrict__ attn, float* __restrict__ Abd)
{
    int b = blockIdx.x;
    float* A = Abd + b * (CDIM * CDIM);
    for (int i = threadIdx.x; i < CDIM * CDIM; i += blockDim.x) A[i] = 0.f;
    __syncthreads();
    for (int t = threadIdx.x; t < 4 * 784; t += blockDim.x) {
        int h = t / 784;
        int r = t - h * 784;
        int d = r / 28, e = r - d * 28;
        A[(h * 28 + e) * CDIM + (h * 28 + d)] = attn[((b * 4 + h) * 28 + d) * 28 + e];
    }
}

// -------------------- 3x3 depthwise conv (+optional GELU) ------------------
__global__ void dw3x3_kernel(const float* __restrict__ in, const float* __restrict__ w,
                             float* __restrict__ outp, int do_gelu)
{
    __shared__ float w_s[112 * 9];
    for (int e = threadIdx.x; e < 1008; e += blockDim.x) w_s[e] = w[e];
    __syncthreads();
    int idx = blockIdx.x * blockDim.x + threadIdx.x;
    if (idx >= 29360128) return;
    int ch = idx % CDIM;
    int p = idx / CDIM;
    int x = p % 256;
    int rest = p / 256;
    int y = rest % 256;
    int b = rest / 256;
    float acc = 0.f;
    #pragma unroll
    for (int dy = -1; dy <= 1; dy++) {
        int yy = y + dy;
        if ((unsigned)yy >= 256u) continue;
        #pragma unroll
        for (int dx = -1; dx <= 1; dx++) {
            int xx = x + dx;
            if ((unsigned)xx >= 256u) continue;
            acc = fmaf(in[((b * 256 + yy) * 256 + xx) * CDIM + ch],
                       w_s[ch * 9 + (dy + 1) * 3 + (dx + 1)], acc);
        }
    }
    if (do_gelu) acc = 0.5f * acc * (1.f + erff(acc * 0.70710678118654752f));
    outp[idx] = acc;
}

// ------------------------------- launch ------------------------------------
extern "C" void kernel_launch(void* const* d_in, const int* in_sizes, int n_in,
                              void* d_out, int out_size)
{
    const float* x_in    = (const float*)d_in[0];
    const float* mask    = (const float*)d_in[1];
    const float* Wq      = (const float*)d_in[2];
    const float* Wk      = (const float*)d_in[3];
    const float* Wv      = (const float*)d_in[4];
    const float* rescale = (const float*)d_in[5];
    const float* proj_w  = (const float*)d_in[6];
    const float* proj_b  = (const float*)d_in[7];
    const float* pe_w1   = (const float*)d_in[8];
    const float* pe_w2   = (const float*)d_in[9];
    const float* c1w     = (const float*)d_in[10];
    const float* c1b     = (const float*)d_in[11];
    const float* c2w     = (const float*)d_in[12];
    const float* c2b     = (const float*)d_in[13];
    const float* dww     = (const float*)d_in[14];
    const float* dwb     = (const float*)d_in[15];
    float* out = (float*)d_out;

    float *q, *k, *v, *xo, *t1, *pe, *m1, *m2, *ms, *ma, *gram, *nq, *nk, *attn, *Abd;
    cudaGetSymbolAddress((void**)&q,    g_q);
    cudaGetSymbolAddress((void**)&k,    g_k);
    cudaGetSymbolAddress((void**)&v,    g_v);
    cudaGetSymbolAddress((void**)&xo,   g_xo);
    cudaGetSymbolAddress((void**)&t1,   g_t1);
    cudaGetSymbolAddress((void**)&pe,   g_pe);
    cudaGetSymbolAddress((void**)&m1,   g_m1);
    cudaGetSymbolAddress((void**)&m2,   g_m2);
    cudaGetSymbolAddress((void**)&ms,   g_ms);
    cudaGetSymbolAddress((void**)&ma,   g_ma);
    cudaGetSymbolAddress((void**)&gram, g_gram);
    cudaGetSymbolAddress((void**)&nq,   g_nq);
    cudaGetSymbolAddress((void**)&nk,   g_nk);
    cudaGetSymbolAddress((void**)&attn, g_attn);
    cudaGetSymbolAddress((void**)&Abd,  g_Abd);

    const size_t smem = (CDIM * CDIM + 128 * 113) * sizeof(float); // 108032
    cudaFuncSetAttribute((const void*)gemm112<true,  false, false, false>,
                         cudaFuncAttributeMaxDynamicSharedMemorySize, (int)smem);
    cudaFuncSetAttribute((const void*)gemm112<false, false, false, false>,
                         cudaFuncAttributeMaxDynamicSharedMemorySize, (int)smem);
    cudaFuncSetAttribute((const void*)gemm112<false, true,  false, true>,
                         cudaFuncAttributeMaxDynamicSharedMemorySize, (int)smem);
    cudaFuncSetAttribute((const void*)gemm112<false, false, true,  false>,
                         cudaFuncAttributeMaxDynamicSharedMemorySize, (int)smem);

    // 0) zero gram accumulator (fresh every replay for determinism)
    zero_small_kernel<<<49, 256>>>(gram);

    // 1) mask pipeline (exact fp32) — grid/bounds now cover all 13,705,216
    gemm112<true,  false, false, false><<<956, 224, smem>>>(mask, c1w, c1b, nullptr, nullptr, m1, MROWS);
    gemm112<true,  false, false, false><<<956, 224, smem>>>(m1,   c2w, c2b, nullptr, nullptr, m2, MROWS);
    mask_dw_kernel<<<53536, 256>>>(m1, m2, dww, dwb, ms);
    shift_kernel<<<28672, 256>>>(ms, ma);

    // 2) QKV projections (exact fp32, packed f32x2)
    gemm112<false, false, false, false><<<2048, 224, smem>>>(x_in, Wq, nullptr, nullptr, nullptr, q, ROWS_TOTAL);
    gemm112<false, false, false, false><<<2048, 224, smem>>>(x_in, Wk, nullptr, nullptr, nullptr, k, ROWS_TOTAL);
    gemm112<false, false, false, false><<<2048, 224, smem>>>(x_in, Wv, nullptr, nullptr, nullptr, v, ROWS_TOTAL);

    // 3) literal column norms, then literal normalized gram (exact fp32)
    norm_lit_kernel<<<dim3(CDIM, 4), 256>>>(q, nq);
    norm_lit_kernel<<<dim3(CDIM, 4), 256>>>(k, nk);
    gram_lit_kernel<<<dim3(128, 16), 784>>>(q, k, nq, nk, gram);

    // 4) rescale + softmax; build block-diagonal apply matrix
    attn_softmax_kernel<<<16, 784>>>(gram, rescale, attn);
    build_abd_kernel<<<4, 256>>>(attn, Abd);

    // 5) positional-encoding branch (exact fp32)
    dw3x3_kernel<<<114688, 256>>>(v,  pe_w1, t1, 1);
    dw3x3_kernel<<<114688, 256>>>(t1, pe_w2, pe, 0);

    // 6) attention apply: xo = (v ⊙ ma) @ Abd[b]
    gemm112<false, true,  false, true ><<<2048, 224, smem>>>(v, Abd, nullptr, ma, nullptr, xo, ROWS_TOTAL);

    // 7) output projection: out = xo @ proj_w + proj_b + pe
    gemm112<false, false, true,  false><<<2048, 224, smem>>>(xo, proj_w, proj_b, nullptr, pe, out, ROWS_TOTAL);
}

// round 17
// speedup vs baseline: 1.0142x; 1.0016x over previous
#include <cuda_runtime.h>
#include <math.h>

// ---------------------------------------------------------------------------
// MS_MSA — exact fp32, f32x2 GEMMs. FIX: mask-buffer size constant was
// 13704448 (768 short of 122368*112=13705216) since R1 — overflow corrupted
// the ms tail -> 64 mask_attn entries -> stable 1.4475e-3 deviation.
// B=4, H=W=256, C=112, HEADS=4, D=28, N=65536, WP=478
// ---------------------------------------------------------------------------

#define CDIM 112
#define NPIX 65536
#define ROWS_TOTAL 262144   // 4*65536
#define MROWS 122368        // 256*478
#define MELEMS 13705216     // 122368*112  (was wrongly 13704448)
#define WPW 478

typedef unsigned long long u64;

__device__ __forceinline__ u64 pk2(float a) {
    u64 r; asm("mov.b64 %0, {%1, %1};" : "=l"(r) : "f"(a)); return r;
}
__device__ __forceinline__ u64 fma2(u64 a, u64 b, u64 c) {
    u64 d; asm("fma.rn.f32x2 %0, %1, %2, %3;" : "=l"(d) : "l"(a), "l"(b), "l"(c)); return d;
}
__device__ __forceinline__ float lo32(u64 v){ return __uint_as_float((unsigned)(v & 0xffffffffu)); }
__device__ __forceinline__ float hi32(u64 v){ return __uint_as_float((unsigned)(v >> 32)); }

// ------------------------- scratch (device globals) ------------------------
__device__ float g_q[29360128];
__device__ float g_k[29360128];
__device__ float g_v[29360128];
__device__ float g_xo[29360128];
__device__ float g_t1[29360128];
__device__ float g_pe[29360128];
__device__ float g_m1[13705216];
__device__ float g_m2[13705216];
__device__ float g_ms[13705216];
__device__ float g_ma[7340032];       // mask_attn [256,256,112]
__device__ float g_gram[12544];       // [4][4][28][28] normalized k.q
__device__ float g_nq[448];           // [4][112] sum of squares
__device__ float g_nk[448];
__device__ float g_attn[12544];
__device__ float g_Abd[50176];        // [4][112][112] block-diag apply matrix

// ------------------------------- zero kernel -------------------------------
__global__ void zero_small_kernel(float* gram) {
    int t = blockIdx.x * blockDim.x + threadIdx.x;
    if (t < 12544) gram[t] = 0.f;
}

// ------------------------- generic 112-wide GEMM ---------------------------
// out[r, o] = sum_i A'[r,i] * Weff[i,o]  (+bias) (+add);  exact fp32.
template<bool TRANSW, bool HAS_MUL, bool HAS_ADD, bool WPERB>
__global__ __launch_bounds__(224, 2)
void gemm112(const float* __restrict__ A, const float* __restrict__ W,
             const float* __restrict__ bias, const float* __restrict__ mul,
             const float* __restrict__ add, float* __restrict__ out, int rows)
{
    extern __shared__ float sm[];
    float* w_s = sm;                 // [112][112]
    float* x_s = sm + CDIM * CDIM;   // [128][113]
    const int tid = threadIdx.x;
    const int r0 = blockIdx.x * 128;

    const float* Wp = W;
    if (WPERB) Wp += (r0 >> 16) * (CDIM * CDIM);

    for (int e = tid; e < CDIM * CDIM; e += 224) {
        if (TRANSW) { int o = e / CDIM, i = e - o * CDIM; w_s[i * CDIM + o] = Wp[e]; }
        else        { w_s[e] = Wp[e]; }
    }
    for (int e = tid; e < 128 * CDIM; e += 224) {
        int r = e / CDIM, i = e - r * CDIM;
        int gr = r0 + r;
        float v = 0.f;
        if (gr < rows) {
            v = A[gr * CDIM + i];
            if (HAS_MUL) v = v * mul[(gr & (NPIX - 1)) * CDIM + i];
        }
        x_s[r * 113 + i] = v;
    }
    __syncthreads();

    const int rg = tid / 14, cg = tid - rg * 14;
    const int o0 = cg * 8;
    const int rbase = rg * 8;
    u64 acc[8][4];
    #pragma unroll
    for (int a = 0; a < 8; a++)
        #pragma unroll
        for (int b = 0; b < 4; b++) acc[a][b] = 0ull;

    const float* xp = &x_s[rbase * 113];
    #pragma unroll 4
    for (int i = 0; i < CDIM; i++) {
        ulonglong2 w0 = *reinterpret_cast<const ulonglong2*>(&w_s[i * CDIM + o0]);
        ulonglong2 w1 = *reinterpret_cast<const ulonglong2*>(&w_s[i * CDIM + o0 + 4]);
        #pragma unroll
        for (int rr = 0; rr < 8; rr++) {
            u64 xx = pk2(xp[rr * 113 + i]);
            acc[rr][0] = fma2(xx, w0.x, acc[rr][0]);
            acc[rr][1] = fma2(xx, w0.y, acc[rr][1]);
            acc[rr][2] = fma2(xx, w1.x, acc[rr][2]);
            acc[rr][3] = fma2(xx, w1.y, acc[rr][3]);
        }
    }

    #pragma unroll
    for (int rr = 0; rr < 8; rr++) {
        int gr = r0 + rbase + rr;
        if (gr >= rows) continue;
        float o_[8];
        o_[0] = lo32(acc[rr][0]); o_[1] = hi32(acc[rr][0]);
        o_[2] = lo32(acc[rr][1]); o_[3] = hi32(acc[rr][1]);
        o_[4] = lo32(acc[rr][2]); o_[5] = hi32(acc[rr][2]);
        o_[6] = lo32(acc[rr][3]); o_[7] = hi32(acc[rr][3]);
        #pragma unroll
        for (int cc = 0; cc < 8; cc++) {
            float vv = o_[cc];
            if (bias)    vv += bias[o0 + cc];
            if (HAS_ADD) vv += add[gr * CDIM + o0 + cc];
            o_[cc] = vv;
        }
        float4* op = reinterpret_cast<float4*>(&out[gr * CDIM + o0]);
        op[0] = make_float4(o_[0], o_[1], o_[2], o_[3]);
        op[1] = make_float4(o_[4], o_[5], o_[6], o_[7]);
    }
}

// --------------- 5x5 depthwise + sigmoid + combine (ms = m1*amap + m1) -----
__global__ void mask_dw_kernel(const float* __restrict__ m1, const float* __restrict__ m2,
                               const float* __restrict__ dww, const float* __restrict__ dwb,
                               float* __restrict__ ms)
{
    __shared__ float w_s[112 * 25];
    __shared__ float b_s[112];
    for (int e = threadIdx.x; e < 112 * 25; e += blockDim.x) w_s[e] = dww[e];
    if (threadIdx.x < 112) b_s[threadIdx.x] = dwb[threadIdx.x];
    __syncthreads();
    int idx = blockIdx.x * blockDim.x + threadIdx.x;
    if (idx >= MELEMS) return;
    int ch = idx % CDIM;
    int p = idx / CDIM;
    int xc = p % WPW;
    int y = p / WPW;
    float acc = b_s[ch];
    #pragma unroll
    for (int dy = -2; dy <= 2; dy++) {
        int yy = y + dy;
        if ((unsigned)yy >= 256u) continue;
        #pragma unroll
        for (int dx = -2; dx <= 2; dx++) {
            int xx = xc + dx;
            if ((unsigned)xx >= (unsigned)WPW) continue;
            acc = fmaf(m2[(yy * WPW + xx) * CDIM + ch],
                       w_s[ch * 25 + (dy + 2) * 5 + (dx + 2)], acc);
        }
    }
    float amap = 1.f / (1.f + expf(-acc));
    float m1v = m1[idx];
    ms[idx] = m1v * amap + m1v;
}

// --------------------------- per-channel shift -----------------------------
// mask_attn[y, xo, ch] = ms[y, 2*ch + xo, ch]
__global__ void shift_kernel(const float* __restrict__ ms, float* __restrict__ ma)
{
    int idx = blockIdx.x * blockDim.x + threadIdx.x;
    if (idx >= 7340032) return;
    int ch = idx % CDIM;
    int p = idx / CDIM;
    int xo = p % 256;
    int y = p / 256;
    ma[idx] = ms[(y * WPW + 2 * ch + xo) * CDIM + ch];
}

// --------------------- literal per-(b,c) column norms ----------------------
__global__ void norm_lit_kernel(const float* __restrict__ x, float* __restrict__ outp)
{
    __shared__ float red[256];
    int c = blockIdx.x, b = blockIdx.y;
    float s = 0.f;
    for (int n = threadIdx.x; n < NPIX; n += 256) {
        float v = x[(b * NPIX + n) * CDIM + c];
        s = fmaf(v, v, s);
    }
    red[threadIdx.x] = s;
    __syncthreads();
    for (int st = 128; st > 0; st >>= 1) {
        if (threadIdx.x < st) red[threadIdx.x] += red[threadIdx.x + st];
        __syncthreads();
    }
    if (threadIdx.x == 0) outp[b * CDIM + c] = red[0];
}

// ---------- literal gram: thread (d,e) owns attn[b,h,d,e] partial ----------
__global__ void gram_lit_kernel(const float* __restrict__ q, const float* __restrict__ k,
                                const float* __restrict__ nqs, const float* __restrict__ nks,
                                float* __restrict__ gram)
{
    __shared__ float qt[64][29];
    __shared__ float kt[64][29];
    __shared__ float qn[28], kn[28];
    const int bh = blockIdx.y;
    const int b = bh >> 2, h = bh & 3;
    const int base = b * NPIX + blockIdx.x * 512;
    const int t = threadIdx.x;

    if (t < 28)      qn[t]      = fmaxf(sqrtf(nqs[b * CDIM + h * 28 + t]), 1e-12f);
    else if (t < 56) kn[t - 28] = fmaxf(sqrtf(nks[b * CDIM + h * 28 + (t - 28)]), 1e-12f);
    __syncthreads();

    const int d = t / 28, e = t - d * 28;
    float acc = 0.f;
    for (int c0 = 0; c0 < 512; c0 += 64) {
        for (int i = t; i < 64 * 28; i += 784) {
            int rr = i / 28, ch = i - rr * 28;
            int r = base + c0 + rr;
            qt[rr][ch] = q[r * CDIM + h * 28 + ch] / qn[ch];
            kt[rr][ch] = k[r * CDIM + h * 28 + ch] / kn[ch];
        }
        __syncthreads();
        #pragma unroll 8
        for (int rr = 0; rr < 64; rr++)
            acc = fmaf(kt[rr][d], qt[rr][e], acc);
        __syncthreads();
    }
    atomicAdd(&gram[bh * 784 + d * 28 + e], acc);
}

// ------------------ finalize attention: rescale + softmax ------------------
__global__ void attn_softmax_kernel(const float* __restrict__ gram, const float* __restrict__ rescale,
                                    float* __restrict__ attn)
{
    __shared__ float s[28][28];
    __shared__ float sex[28][28];
    int bh = blockIdx.x;
    int h = bh & 3;
    int t = threadIdx.x;
    int d = t / 28, e = t - d * 28;
    float v = gram[bh * 784 + d * 28 + e] * rescale[h];
    s[d][e] = v;
    __syncthreads();
    float m = -1e30f;
    for (int j = 0; j < 28; j++) m = fmaxf(m, s[d][j]);
    float ex = expf(v - m);
    sex[d][e] = ex;
    __syncthreads();
    float sum = 0.f;
    for (int j = 0; j < 28; j++) sum += sex[d][j];
    attn[bh * 784 + d * 28 + e] = ex / sum;
}

// ---- build block-diagonal apply matrix: Abd[b][h*28+e][h*28+d]=attn[b,h,d,e]
__global__ void build_abd_kernel(const float* __restrict__ attn, float* __restrict__ Abd)
{
    int b = blockIdx.x;
    float* A = Abd + b * (CDIM * CDIM);
    for (int i = threadIdx.x; i < CDIM * CDIM; i += blockDim.x) A[i] = 0.f;
    __syncthreads();
    for (int t = threadIdx.x; t < 4 * 784; t += blockDim.x) {
        int h = t / 784;
        int r = t - h * 784;
        int d = r / 28, e = r - d * 28;
        A[(h * 28 + e) * CDIM + (h * 28 + d)] = attn[((b * 4 + h) * 28 + d) * 28 + e];
    }
}

// -------------------- 3x3 depthwise conv (+optional GELU) ------------------
__global__ void dw3x3_kernel(const float* __restrict__ in, const float* __restrict__ w,
                             float* __restrict__ outp, int do_gelu)
{
    __shared__ float w_s[112 * 9];
    for (int e = threadIdx.x; e < 1008; e += blockDim.x) w_s[e] = w[e];
    __syncthreads();
    int idx = blockIdx.x * blockDim.x + threadIdx.x;
    if (idx >= 29360128) return;
    int ch = idx % CDIM;
    int p = idx / CDIM;
    int x = p % 256;
    int rest = p / 256;
    int y = rest % 256;
    int b = rest / 256;
    float acc = 0.f;
    #pragma unroll
    for (int dy = -1; dy <= 1; dy++) {
        int yy = y + dy;
        if ((unsigned)yy >= 256u) continue;
        #pragma unroll
        for (int dx = -1; dx <= 1; dx++) {
            int xx = x + dx;
            if ((unsigned)xx >= 256u) continue;
            acc = fmaf(in[((b * 256 + yy) * 256 + xx) * CDIM + ch],
                       w_s[ch * 9 + (dy + 1) * 3 + (dx + 1)], acc);
        }
    }
    if (do_gelu) acc = 0.5f * acc * (1.f + erff(acc * 0.70710678118654752f));
    outp[idx] = acc;
}

// ------------------------------- launch ------------------------------------
extern "C" void kernel_launch(void* const* d_in, const int* in_sizes, int n_in,
                              void* d_out, int out_size)
{
    const float* x_in    = (const float*)d_in[0];
    const float* mask    = (const float*)d_in[1];
    const float* Wq      = (const float*)d_in[2];
    const float* Wk      = (const float*)d_in[3];
    const float* Wv      = (const float*)d_in[4];
    const float* rescale = (const float*)d_in[5];
    const float* proj_w  = (const float*)d_in[6];
    const float* proj_b  = (const float*)d_in[7];
    const float* pe_w1   = (const float*)d_in[8];
    const float* pe_w2   = (const float*)d_in[9];
    const float* c1w     = (const float*)d_in[10];
    const float* c1b     = (const float*)d_in[11];
    const float* c2w     = (const float*)d_in[12];
    const float* c2b     = (const float*)d_in[13];
    const float* dww     = (const float*)d_in[14];
    const float* dwb     = (const float*)d_in[15];
    float* out = (float*)d_out;

    float *q, *k, *v, *xo, *t1, *pe, *m1, *m2, *ms, *ma, *gram, *nq, *nk, *attn, *Abd;
    cudaGetSymbolAddress((void**)&q,    g_q);
    cudaGetSymbolAddress((void**)&k,    g_k);
    cudaGetSymbolAddress((void**)&v,    g_v);
    cudaGetSymbolAddress((void**)&xo,   g_xo);
    cudaGetSymbolAddress((void**)&t1,   g_t1);
    cudaGetSymbolAddress((void**)&pe,   g_pe);
    cudaGetSymbolAddress((void**)&m1,   g_m1);
    cudaGetSymbolAddress((void**)&m2,   g_m2);
    cudaGetSymbolAddress((void**)&ms,   g_ms);
    cudaGetSymbolAddress((void**)&ma,   g_ma);
    cudaGetSymbolAddress((void**)&gram, g_gram);
    cudaGetSymbolAddress((void**)&nq,   g_nq);
    cudaGetSymbolAddress((void**)&nk,   g_nk);
    cudaGetSymbolAddress((void**)&attn, g_attn);
    cudaGetSymbolAddress((void**)&Abd,  g_Abd);

    const size_t smem = (CDIM * CDIM + 128 * 113) * sizeof(float); // 108032
    cudaFuncSetAttribute((const void*)gemm112<true,  false, false, false>,
                         cudaFuncAttributeMaxDynamicSharedMemorySize, (int)smem);
    cudaFuncSetAttribute((const void*)gemm112<false, false, false, false>,
                         cudaFuncAttributeMaxDynamicSharedMemorySize, (int)smem);
    cudaFuncSetAttribute((const void*)gemm112<false, true,  false, true>,
                         cudaFuncAttributeMaxDynamicSharedMemorySize, (int)smem);
    cudaFuncSetAttribute((const void*)gemm112<false, false, true,  false>,
                         cudaFuncAttributeMaxDynamicSharedMemorySize, (int)smem);

    // 0) zero gram accumulator (fresh every replay for determinism)
    zero_small_kernel<<<49, 256>>>(gram);

    // 1) mask pipeline (exact fp32) — grid/bounds now cover all 13,705,216
    gemm112<true,  false, false, false><<<956, 224, smem>>>(mask, c1w, c1b, nullptr, nullptr, m1, MROWS);
    gemm112<true,  false, false, false><<<956, 224, smem>>>(m1,   c2w, c2b, nullptr, nullptr, m2, MROWS);
    mask_dw_kernel<<<53536, 256>>>(m1, m2, dww, dwb, ms);
    shift_kernel<<<28672, 256>>>(ms, ma);

    // 2) QKV projections (exact fp32, packed f32x2)
    gemm112<false, false, false, false><<<2048, 224, smem>>>(x_in, Wq, nullptr, nullptr, nullptr, q, ROWS_TOTAL);
    gemm112<false, false, false, false><<<2048, 224, smem>>>(x_in, Wk, nullptr, nullptr, nullptr, k, ROWS_TOTAL);
    gemm112<false, false, false, false><<<2048, 224, smem>>>(x_in, Wv, nullptr, nullptr, nullptr, v, ROWS_TOTAL);

    // 3) literal column norms, then literal normalized gram (exact fp32)
    norm_lit_kernel<<<dim3(CDIM, 4), 256>>>(q, nq);
    norm_lit_kernel<<<dim3(CDIM, 4), 256>>>(k, nk);
    gram_lit_kernel<<<dim3(128, 16), 784>>>(q, k, nq, nk, gram);

    // 4) rescale + softmax; build block-diagonal apply matrix
    attn_softmax_kernel<<<16, 784>>>(gram, rescale, attn);
    build_abd_kernel<<<4, 256>>>(attn, Abd);

    // 5) positional-encoding branch (exact fp32)
    dw3x3_kernel<<<114688, 256>>>(v,  pe_w1, t1, 1);
    dw3x3_kernel<<<114688, 256>>>(t1, pe_w2, pe, 0);

    // 6) attention apply: xo = (v ⊙ ma) @ Abd[b]
    gemm112<false, true,  false, true ><<<2048, 224, smem>>>(v, Abd, nullptr, ma, nullptr, xo, ROWS_TOTAL);

    // 7) output projection: out = xo @ proj_w + proj_b + pe
    gemm112<false, false, true,  false><<<2048, 224, smem>>>(xo, proj_w, proj_b, nullptr, pe, out, ROWS_TOTAL);
}